// round 5
// baseline (speedup 1.0000x reference)
#include <cuda_runtime.h>
#include <cstdint>
#include <cstddef>

#define DEV __device__ __forceinline__
#define HD __host__ __device__

static constexpr double kPI = 3.14159265358979323846;

// ---------------- constexpr math (compile-time tables) ----------------
HD constexpr double creduce(double x){
  while (x >  kPI) x -= 2.0 * kPI;
  while (x < -kPI) x += 2.0 * kPI;
  return x;
}
HD constexpr double csin(double x){
  x = creduce(x);
  double t = x, s = x, x2 = x * x;
  for (int i = 1; i < 26; ++i){ t *= -x2 / (double)((2*i) * (2*i + 1)); s += t; }
  return s;
}
HD constexpr double ccos(double x){
  x = creduce(x);
  double t = 1.0, s = 1.0, x2 = x * x;
  for (int i = 1; i < 26; ++i){ t *= -x2 / (double)((2*i - 1) * (2*i)); s += t; }
  return s;
}
HD constexpr double clog(double x){
  double r = x, k = 0.0;
  while (r > 1.25) { r *= 0.5; k += 1.0; }
  while (r < 0.75) { r *= 2.0; k -= 1.0; }
  double z = (r - 1.0) / (r + 1.0), z2 = z * z, term = z, s = z;
  for (int i = 1; i < 60; ++i){ term *= z2; s += term / (double)(2*i + 1); }
  return 2.0 * s + k * 0.69314718055994530942;
}

// ---------------- mel filterbank, 2-sparse per spectral bin ----------------
HD constexpr double hz2mel(double f){ return 1127.0 * clog(1.0 + f / 700.0); }
HD constexpr double mel_lo(){ return hz2mel(80.0); }
HD constexpr double mel_step(){ return (hz2mel(7600.0) - hz2mel(80.0)) / 81.0; }
HD constexpr double bin_mel(int k){ return hz2mel(8000.0 * (double)k / 64.0); }

struct MelEnt { int ja; int jb; float wa; float wb; };

// Each bin k (1..64) feeds at most filters i-1 (upper slope) and i (lower slope).
// Window is pre-halved (folds real-split 0.5); bins 32/64 need x2 -> folded here.
HD constexpr MelEnt mel_ent(int k){
  MelEnt e{-1, -1, 0.0f, 0.0f};
  double u = (bin_mel(k) - mel_lo()) / mel_step();
  if (u <= 0.0 || u >= 81.0) return e;
  int i = (int)u;
  double scale = (k == 32 || k == 64) ? 2.0 : 1.0;
  double wu = ((double)(i + 1) - u) * scale;
  double wl = (u - (double)i) * scale;
  if (i - 1 >= 0 && i - 1 <= 79){ e.ja = i - 1; e.wa = (float)wu; }
  if (i <= 79){ e.jb = i; e.wb = (float)wl; }
  return e;
}

// Emission order of bins = exact runtime order: (1,63),(2,62),...,(31,33), then 32.
HD constexpr int emit_bin(int idx){
  if (idx < 62){ int i = idx >> 1; return (idx & 1) ? (63 - i) : (i + 1); }
  return 32;
}
HD constexpr int targ(int bin, int slot){
  MelEnt e = mel_ent(bin);
  return slot ? e.jb : e.ja;
}
HD constexpr int emit_pos(int bin){
  for (int idx = 0; idx < 63; ++idx) if (emit_bin(idx) == bin) return idx;
  return -1;
}
// First writer of a mel register uses '='.
HD constexpr bool is_first_touch(int bin, int slot){
  int j = targ(bin, slot);
  if (j < 0) return false;
  int pos = emit_pos(bin);
  for (int idx = 0; idx < pos; ++idx){
    int b2 = emit_bin(idx);
    if (targ(b2, 0) == j || targ(b2, 1) == j) return false;
  }
  if (slot == 1 && targ(bin, 0) == j) return false;
  return true;
}
// Last writer of filter j: no bin emitted later touches j.
HD constexpr bool is_last_touch(int bin, int slot){
  int j = targ(bin, slot);
  if (j < 0) return false;
  int pos = emit_pos(bin);
  for (int idx = pos + 1; idx < 63; ++idx){
    int b2 = emit_bin(idx);
    if (targ(b2, 0) == j || targ(b2, 1) == j) return false;
  }
  if (slot == 0 && targ(bin, 1) == j) return false;   // (cannot happen; safety)
  return true;
}
HD constexpr bool mel_used(int j){
  for (int idx = 0; idx < 63; ++idx){
    int b2 = emit_bin(idx);
    if (targ(b2, 0) == j || targ(b2, 1) == j) return true;
  }
  return false;
}
HD constexpr int bitrev6(int n){
  int r = 0;
  for (int b = 0; b < 6; ++b) r |= ((n >> b) & 1) << (5 - b);
  return r;
}

// pre-halved Hann window: 0.5 * (0.5 - 0.5*cos(2*pi*m/128))
HD constexpr float hwin(int m){
  return (float)(0.5 * (0.5 - 0.5 * ccos(2.0 * kPI * (double)m / 128.0)));
}

// ---------------- magnitude: MUFU.SQRT, floor guard via FMNMX ----------------
DEV float magf(float re, float im){
  float p2 = fmaf(re, re, im * im);
  p2 = fmaxf(p2, 1e-37f);
  float m;
  asm("sqrt.approx.f32 %0, %1;" : "=f"(m) : "f"(p2));
  return m;
}

// ---------------- mel contribution: route last touch straight to SMEM ----------------
template<int BIN, int SLOT>
DEV void contrib1(float* mel, float* dst, float mag){
  constexpr MelEnt e = mel_ent(BIN);
  constexpr int j = SLOT ? e.jb : e.ja;
  if constexpr (j >= 0){
    constexpr float w = SLOT ? e.wb : e.wa;
    constexpr bool ft = is_first_touch(BIN, SLOT);
    constexpr bool lt = is_last_touch(BIN, SLOT);
    if constexpr (ft && lt)  dst[j] = w * mag;                 // single-contribution filter
    else if constexpr (ft)   mel[j] = w * mag;
    else if constexpr (lt)   dst[j] = fmaf(w, mag, mel[j]);    // register dies here
    else                     mel[j] = fmaf(w, mag, mel[j]);
  }
}
template<int BIN>
DEV void scatter(float* mel, float* dst, float mag){
  contrib1<BIN, 0>(mel, dst, mag);
  contrib1<BIN, 1>(mel, dst, mag);
}

// ---------------- zero-fill for never-touched filters ----------------
template<int J> struct ZeroLoop {
  static DEV void run(float* dst){
    if constexpr (!mel_used(J)) dst[J] = 0.0f;
    ZeroLoop<J + 1>::run(dst);
  }
};
template<> struct ZeroLoop<80>{ static DEV void run(float*){} };

// ---------------- fused window + bit-reversed load + stage-0 butterfly ----------------
template<int M> struct Fused0 {
  static DEV void run(float* Ar, float* Ai, const float* sx, int tid){
    constexpr int s0 = bitrev6(2*M);
    constexpr int s1 = bitrev6(2*M + 1);          // = s0 + 32
    constexpr float w0r = hwin(2*s0), w0i = hwin(2*s0 + 1);
    constexpr float w1r = hwin(2*s1), w1i = hwin(2*s1 + 1);
    float x0r = sx[tid + 2*s0], x0i = sx[tid + 2*s0 + 1];
    float x1r = sx[tid + 2*s1], x1i = sx[tid + 2*s1 + 1];
    float tr = x1r * w1r;
    float ti = x1i * w1i;
    if constexpr (w0r == 0.0f){                   // only s0 == 0 (window zero at m=0)
      Ar[2*M]     = tr;
      Ar[2*M + 1] = -tr;
    } else {
      Ar[2*M]     = fmaf(x0r, w0r,  tr);
      Ar[2*M + 1] = fmaf(x0r, w0r, -tr);
    }
    Ai[2*M]     = fmaf(x0i, w0i,  ti);
    Ai[2*M + 1] = fmaf(x0i, w0i, -ti);
    Fused0<M + 1>::run(Ar, Ai, sx, tid);
  }
};
template<> struct Fused0<32>{ static DEV void run(float*, float*, const float*, int){} };

// ---------------- radix-2 DIT complex FFT-64, fully unrolled, immediate twiddles ----------------
template<int S, int M> struct BflyLoop {
  static DEV void run(float* Ar, float* Ai){
    constexpr int half = 1 << S;
    constexpr int j  = M & (half - 1);
    constexpr int i0 = ((M >> S) << (S + 1)) + j;
    constexpr int i1 = i0 + half;
    float br_ = Ar[i1], bi_ = Ai[i1];
    float tr, ti;
    if constexpr (j == 0){ tr = br_; ti = bi_; }
    else if constexpr (2*j == half){ tr = bi_; ti = -br_; }          // w = -i
    else {
      constexpr float c = (float)ccos(kPI * (double)j / (double)half);
      constexpr float s = (float)csin(kPI * (double)j / (double)half);
      // w = e^{-i*pi*j/half} = (c, -s)
      tr = fmaf(c, br_,  s * bi_);
      ti = fmaf(c, bi_, -(s * br_));
    }
    float ar_ = Ar[i0], ai_ = Ai[i0];
    Ar[i0] = ar_ + tr; Ai[i0] = ai_ + ti;
    Ar[i1] = ar_ - tr; Ai[i1] = ai_ - ti;
    BflyLoop<S, M + 1>::run(Ar, Ai);
  }
};
template<int S> struct BflyLoop<S, 32>{ static DEV void run(float*, float*){} };
template<int S> struct StageLoop {
  static DEV void run(float* Ar, float* Ai){
    BflyLoop<S, 0>::run(Ar, Ai);
    StageLoop<S + 1>::run(Ar, Ai);
  }
};
template<> struct StageLoop<6>{ static DEV void run(float*, float*){} };

// ---------------- real-split + magnitude + mel scatter, per conjugate pair ----------------
template<int K>
DEV void do_pair(float* Ar, float* Ai, float* mel, float* dst){
  float P = Ar[K],      Q = Ai[K];
  float R = Ar[64 - K], S = Ai[64 - K];
  float zer = P + R, zei = Q - S;
  float zor = Q + S, zoi = R - P;
  constexpr float c = (float)ccos(kPI * (double)K / 64.0);
  constexpr float s = (float)csin(kPI * (double)K / 64.0);
  float A  = fmaf(c, zor,  s * zoi);
  float Bv = fmaf(c, zoi, -(s * zor));
  scatter<K>     (mel, dst, magf(zer + A, zei + Bv));
  scatter<64 - K>(mel, dst, magf(zer - A, Bv - zei));
}
template<int K> struct Pairs {
  static DEV void run(float* Ar, float* Ai, float* mel, float* dst){
    do_pair<K>(Ar, Ai, mel, dst);
    Pairs<K + 1>::run(Ar, Ai, mel, dst);
  }
};
template<> struct Pairs<32>{ static DEV void run(float*, float*, float*, float*){} };

// ---------------- kernel ----------------
static constexpr int TPB = 128;       // one thread = one frame
static constexpr int NCOL = 81;       // 1 raw sample + 80 mel

__global__ void __launch_bounds__(TPB, 4)
mel_kernel(const float* __restrict__ x, float* __restrict__ out){
  __shared__ float sx[TPB + 128];                 // 255 staged samples
  __shared__ __align__(16) float sout[TPB * NCOL];

  const int tid = threadIdx.x;
  const int t0  = blockIdx.x * TPB;
  const float* xrow = x + (size_t)blockIdx.y * 16384;

  #pragma unroll
  for (int i = tid; i < TPB + 127; i += TPB){
    int t = t0 + i;
    sx[i] = (t < 16384) ? xrow[t] : 0.0f;
  }
  __syncthreads();

  float* row = sout + tid * NCOL;                 // stride 81 -> bank-conflict-free
  float Ar[64], Ai[64], mel[80];
  Fused0<0>::run(Ar, Ai, sx, tid);                // window + bitrev load + stage 0
  StageLoop<1>::run(Ar, Ai);                      // stages 1..5
  Pairs<1>::run(Ar, Ai, mel, row + 1);            // pairs 1..31, last-touch -> SMEM
  scatter<32>(mel, row + 1, magf(Ar[32], Ai[32]));// X[32]: |conj| == |.|, x2 folded in weights
  ZeroLoop<0>::run(row + 1);                      // untouched filters -> 0
  row[0] = sx[tid];                               // raw passthrough
  __syncthreads();

  // coalesced float4 copy: 128*81 = 10368 floats = 2592 float4 = 20*128 + 32
  float4* g4 = (float4*)(out + ((size_t)blockIdx.y * 16384 + (size_t)t0) * NCOL);
  const float4* s4 = (const float4*)sout;
  #pragma unroll
  for (int r = 0; r < 20; ++r) g4[tid + 128 * r] = s4[tid + 128 * r];
  if (tid < 32) g4[2560 + tid] = s4[2560 + tid];
}

extern "C" void kernel_launch(void* const* d_in, const int* in_sizes, int n_in,
                              void* d_out, int out_size){
  (void)in_sizes; (void)n_in; (void)out_size;
  const float* x = (const float*)d_in[0];
  float* out = (float*)d_out;
  dim3 grid(16384 / TPB, 16);
  mel_kernel<<<grid, TPB>>>(x, out);
}

// round 6
// speedup vs baseline: 1.0495x; 1.0495x over previous
#include <cuda_runtime.h>
#include <cstdint>
#include <cstddef>

#define DEV __device__ __forceinline__
#define HD __host__ __device__

static constexpr double kPI = 3.14159265358979323846;

// ---------------- constexpr math (compile-time tables) ----------------
HD constexpr double creduce(double x){
  while (x >  kPI) x -= 2.0 * kPI;
  while (x < -kPI) x += 2.0 * kPI;
  return x;
}
HD constexpr double csin(double x){
  x = creduce(x);
  double t = x, s = x, x2 = x * x;
  for (int i = 1; i < 26; ++i){ t *= -x2 / (double)((2*i) * (2*i + 1)); s += t; }
  return s;
}
HD constexpr double ccos(double x){
  x = creduce(x);
  double t = 1.0, s = 1.0, x2 = x * x;
  for (int i = 1; i < 26; ++i){ t *= -x2 / (double)((2*i - 1) * (2*i)); s += t; }
  return s;
}
HD constexpr double clog(double x){
  double r = x, k = 0.0;
  while (r > 1.25) { r *= 0.5; k += 1.0; }
  while (r < 0.75) { r *= 2.0; k -= 1.0; }
  double z = (r - 1.0) / (r + 1.0), z2 = z * z, term = z, s = z;
  for (int i = 1; i < 60; ++i){ term *= z2; s += term / (double)(2*i + 1); }
  return 2.0 * s + k * 0.69314718055994530942;
}

// ---------------- mel filterbank, 2-sparse per spectral bin ----------------
HD constexpr double hz2mel(double f){ return 1127.0 * clog(1.0 + f / 700.0); }
HD constexpr double mel_lo(){ return hz2mel(80.0); }
HD constexpr double mel_step(){ return (hz2mel(7600.0) - hz2mel(80.0)) / 81.0; }
HD constexpr double bin_mel(int k){ return hz2mel(8000.0 * (double)k / 64.0); }

struct MelEnt { int ja; int jb; float wa; float wb; };

HD constexpr MelEnt mel_ent(int k){
  MelEnt e{-1, -1, 0.0f, 0.0f};
  double u = (bin_mel(k) - mel_lo()) / mel_step();
  if (u <= 0.0 || u >= 81.0) return e;
  int i = (int)u;
  double scale = (k == 32 || k == 64) ? 2.0 : 1.0;
  double wu = ((double)(i + 1) - u) * scale;
  double wl = (u - (double)i) * scale;
  if (i - 1 >= 0 && i - 1 <= 79){ e.ja = i - 1; e.wa = (float)wu; }
  if (i <= 79){ e.jb = i; e.wb = (float)wl; }
  return e;
}
HD constexpr bool bin_used(int k){
  MelEnt e = mel_ent(k);
  return e.ja >= 0 || e.jb >= 0;
}

// Emission order of bins: pairs (1,63),(2,62),...,(31,33), then 32.
HD constexpr int emit_bin(int idx){
  if (idx < 62){ int i = idx >> 1; return (idx & 1) ? (63 - i) : (i + 1); }
  return 32;
}
HD constexpr int targ(int bin, int slot){
  MelEnt e = mel_ent(bin);
  return slot ? e.jb : e.ja;
}
HD constexpr bool is_first_touch(int bin, int slot){
  int j = targ(bin, slot);
  if (j < 0) return false;
  int pos = 0;
  for (int idx = 0; idx < 63; ++idx){ if (emit_bin(idx) == bin){ pos = idx; break; } }
  for (int idx = 0; idx < pos; ++idx){
    int b2 = emit_bin(idx);
    if (targ(b2, 0) == j || targ(b2, 1) == j) return false;
  }
  if (slot == 1 && targ(bin, 0) == j) return false;
  return true;
}
HD constexpr bool mel_used(int j){
  for (int idx = 0; idx < 63; ++idx){
    int b2 = emit_bin(idx);
    if (targ(b2, 0) == j || targ(b2, 1) == j) return true;
  }
  return false;
}
HD constexpr int bitrev6(int n){
  int r = 0;
  for (int b = 0; b < 6; ++b) r |= ((n >> b) & 1) << (5 - b);
  return r;
}

// pre-halved Hann window: 0.5 * (0.5 - 0.5*cos(2*pi*m/128))
HD constexpr float hwin(int m){
  return (float)(0.5 * (0.5 - 0.5 * ccos(2.0 * kPI * (double)m / 128.0)));
}

// ---------------- magnitude: MUFU.SQRT, floor guard via FMNMX ----------------
DEV float magf(float re, float im){
  float p2 = fmaf(re, re, im * im);
  p2 = fmaxf(p2, 1e-37f);
  float m;
  asm("sqrt.approx.f32 %0, %1;" : "=f"(m) : "f"(p2));
  return m;
}

// ---------------- mel scatter (static register indices, R2-proven) ----------------
template<int BIN>
DEV void scatter(float* mel, float mag){
  constexpr MelEnt e = mel_ent(BIN);
  if constexpr (e.ja >= 0){
    if constexpr (is_first_touch(BIN, 0)) mel[e.ja] = e.wa * mag;
    else mel[e.ja] = fmaf(e.wa, mag, mel[e.ja]);
  }
  if constexpr (e.jb >= 0){
    if constexpr (is_first_touch(BIN, 1)) mel[e.jb] = e.wb * mag;
    else mel[e.jb] = fmaf(e.wb, mag, mel[e.jb]);
  }
}

// ---------------- fused window + bit-reversed load + stage-0 butterfly ----------------
template<int M> struct Fused0 {
  static DEV void run(float* Ar, float* Ai, const float* sx, int tid){
    constexpr int s0 = bitrev6(2*M);
    constexpr int s1 = bitrev6(2*M + 1);          // = s0 + 32
    constexpr float w0r = hwin(2*s0), w0i = hwin(2*s0 + 1);
    constexpr float w1r = hwin(2*s1), w1i = hwin(2*s1 + 1);
    float x0r = sx[tid + 2*s0], x0i = sx[tid + 2*s0 + 1];
    float x1r = sx[tid + 2*s1], x1i = sx[tid + 2*s1 + 1];
    float tr = x1r * w1r;
    float ti = x1i * w1i;
    if constexpr (w0r == 0.0f){                   // only s0 == 0 (window zero at m=0)
      Ar[2*M]     = tr;
      Ar[2*M + 1] = -tr;
    } else {
      Ar[2*M]     = fmaf(x0r, w0r,  tr);
      Ar[2*M + 1] = fmaf(x0r, w0r, -tr);
    }
    Ai[2*M]     = fmaf(x0i, w0i,  ti);
    Ai[2*M + 1] = fmaf(x0i, w0i, -ti);
    Fused0<M + 1>::run(Ar, Ai, sx, tid);
  }
};
template<> struct Fused0<32>{ static DEV void run(float*, float*, const float*, int){} };

// ---------------- radix-2 stage 1 (all twiddles trivial: 1 and -i) ----------------
template<int M> struct Stage1 {
  static DEV void run(float* Ar, float* Ai){
    constexpr int j  = M & 1;
    constexpr int i0 = ((M >> 1) << 2) + j;
    constexpr int i1 = i0 + 2;
    float br_ = Ar[i1], bi_ = Ai[i1];
    float tr, ti;
    if constexpr (j == 0){ tr = br_; ti = bi_; }
    else { tr = bi_; ti = -br_; }                 // w = -i
    float ar_ = Ar[i0], ai_ = Ai[i0];
    Ar[i0] = ar_ + tr; Ai[i0] = ai_ + ti;
    Ar[i1] = ar_ - tr; Ai[i1] = ai_ - ti;
    Stage1<M + 1>::run(Ar, Ai);
  }
};
template<> struct Stage1<32>{ static DEV void run(float*, float*){} };

// ---------------- radix-4 dragonfly: fuses radix-2 stages S and S+1 ----------------
// Elements i0, i0+h, i0+2h, i0+3h (h = 2^S).  With w = e^{-i*pi*j/(2h)}:
//   u1 = w*x2, u2 = w^2*x1, u3 = w^3*x3
//   r0 = x0+u2, r1 = x0-u2, p = u1+u3, q = u1-u3
//   out[i0]=r0+p, out[i0+2h]=r0-p, out[i0+h]=r1-i*q, out[i0+3h]=r1+i*q
// Verified equal to the two radix-2 stages (stage-S+1 twiddle for the (y1,y3)
// pair is exactly -i*w, absorbed into the free -i*q rotation).
template<int S, int G> struct R4Loop {
  static DEV void run(float* Ar, float* Ai){
    constexpr int h  = 1 << S;
    constexpr int j  = G & (h - 1);
    constexpr int i0 = ((G >> S) << (S + 2)) + j;
    constexpr double ang = kPI * (double)j / (double)(2 * h);
    constexpr float c1 = (float)ccos(2.0 * ang), s1 = (float)csin(2.0 * ang);
    constexpr float c2 = (float)ccos(ang),        s2 = (float)csin(ang);
    constexpr float c3 = (float)ccos(3.0 * ang),  s3 = (float)csin(3.0 * ang);

    float x0r = Ar[i0],       x0i = Ai[i0];
    float x1r = Ar[i0 + h],   x1i = Ai[i0 + h];
    float x2r = Ar[i0 + 2*h], x2i = Ai[i0 + 2*h];
    float x3r = Ar[i0 + 3*h], x3i = Ai[i0 + 3*h];

    float u1r, u1i, u2r, u2i, u3r, u3i;
    if constexpr (j == 0){
      u1r = x2r; u1i = x2i; u2r = x1r; u2i = x1i; u3r = x3r; u3i = x3i;
    } else {
      // u1 = (c2,-s2)*x2 ; u3 = (c3,-s3)*x3
      u1r = fmaf(c2, x2r,  s2 * x2i);
      u1i = fmaf(c2, x2i, -(s2 * x2r));
      u3r = fmaf(c3, x3r,  s3 * x3i);
      u3i = fmaf(c3, x3i, -(s3 * x3r));
      if constexpr (2*j == h){                    // w^2 = -i : free swap
        u2r = x1i; u2i = -x1r;
      } else {
        u2r = fmaf(c1, x1r,  s1 * x1i);
        u2i = fmaf(c1, x1i, -(s1 * x1r));
      }
    }
    float r0r = x0r + u2r, r0i = x0i + u2i;
    float r1r = x0r - u2r, r1i = x0i - u2i;
    float pr  = u1r + u3r, pi  = u1i + u3i;
    float qr  = u1r - u3r, qi  = u1i - u3i;

    Ar[i0]       = r0r + pr;  Ai[i0]       = r0i + pi;
    Ar[i0 + 2*h] = r0r - pr;  Ai[i0 + 2*h] = r0i - pi;
    Ar[i0 + h]   = r1r + qi;  Ai[i0 + h]   = r1i - qr;   // r1 - i*q
    Ar[i0 + 3*h] = r1r - qi;  Ai[i0 + 3*h] = r1i + qr;   // r1 + i*q
    R4Loop<S, G + 1>::run(Ar, Ai);
  }
};
template<int S> struct R4Loop<S, 16>{ static DEV void run(float*, float*){} };

// ---------------- real-split + magnitude + mel scatter, per conjugate pair ----------------
template<int K>
DEV void do_pair(float* Ar, float* Ai, float* mel){
  float P = Ar[K],      Q = Ai[K];
  float R = Ar[64 - K], S = Ai[64 - K];
  float zer = P + R, zei = Q - S;
  float zor = Q + S, zoi = R - P;
  constexpr float c = (float)ccos(kPI * (double)K / 64.0);
  constexpr float s = (float)csin(kPI * (double)K / 64.0);
  float A  = fmaf(c, zor,  s * zoi);
  float Bv = fmaf(c, zoi, -(s * zor));
  scatter<K>(mel, magf(zer + A, zei + Bv));
  if constexpr (bin_used(64 - K)){                // bins 61-63 feed no filter
    scatter<64 - K>(mel, magf(zer - A, Bv - zei));
  }
}
template<int K> struct Pairs {
  static DEV void run(float* Ar, float* Ai, float* mel){
    do_pair<K>(Ar, Ai, mel);
    Pairs<K + 1>::run(Ar, Ai, mel);
  }
};
template<> struct Pairs<32>{ static DEV void run(float*, float*, float*){} };

// ---------------- store mel row to SMEM (untouched bins -> literal 0) ----------------
template<int J> struct StoreLoop {
  static DEV void run(float* dst, const float* mel){
    if constexpr (mel_used(J)) dst[J] = mel[J];
    else dst[J] = 0.0f;
    StoreLoop<J + 1>::run(dst, mel);
  }
};
template<> struct StoreLoop<80>{ static DEV void run(float*, const float*){} };

// ---------------- kernel ----------------
static constexpr int TPB = 128;       // one thread = one frame
static constexpr int NCOL = 81;       // 1 raw sample + 80 mel

__global__ void __launch_bounds__(TPB, 4)
mel_kernel(const float* __restrict__ x, float* __restrict__ out){
  __shared__ float sx[TPB + 128];                 // 255 staged samples
  __shared__ __align__(16) float sout[TPB * NCOL];

  const int tid = threadIdx.x;
  const int t0  = blockIdx.x * TPB;
  const float* xrow = x + (size_t)blockIdx.y * 16384;

  #pragma unroll
  for (int i = tid; i < TPB + 127; i += TPB){
    int t = t0 + i;
    sx[i] = (t < 16384) ? xrow[t] : 0.0f;
  }
  __syncthreads();

  float Ar[64], Ai[64], mel[80];
  Fused0<0>::run(Ar, Ai, sx, tid);                // window + bitrev load + stage 0
  Stage1<0>::run(Ar, Ai);                         // stage 1 (trivial twiddles)
  R4Loop<2, 0>::run(Ar, Ai);                      // stages 2+3 fused radix-4
  R4Loop<4, 0>::run(Ar, Ai);                      // stages 4+5 fused radix-4
  Pairs<1>::run(Ar, Ai, mel);
  scatter<32>(mel, magf(Ar[32], Ai[32]));         // X[32]: |conj| == |.|, x2 folded in weights

  // stage 81-float output row in SMEM (stride 81 -> bank-conflict-free)
  float* row = sout + tid * NCOL;
  row[0] = sx[tid];
  StoreLoop<0>::run(row + 1, mel);
  __syncthreads();

  // coalesced float4 copy: 128*81 = 10368 floats = 2592 float4 = 20*128 + 32
  float4* g4 = (float4*)(out + ((size_t)blockIdx.y * 16384 + (size_t)t0) * NCOL);
  const float4* s4 = (const float4*)sout;
  #pragma unroll
  for (int r = 0; r < 20; ++r) g4[tid + 128 * r] = s4[tid + 128 * r];
  if (tid < 32) g4[2560 + tid] = s4[2560 + tid];
}

extern "C" void kernel_launch(void* const* d_in, const int* in_sizes, int n_in,
                              void* d_out, int out_size){
  (void)in_sizes; (void)n_in; (void)out_size;
  const float* x = (const float*)d_in[0];
  float* out = (float*)d_out;
  dim3 grid(16384 / TPB, 16);
  mel_kernel<<<grid, TPB>>>(x, out);
}

// round 7
// speedup vs baseline: 1.0714x; 1.0209x over previous
#include <cuda_runtime.h>
#include <cstdint>
#include <cstddef>

#define DEV __device__ __forceinline__
#define HD __host__ __device__

static constexpr double kPI = 3.14159265358979323846;

// ---------------- constexpr math (compile-time tables) ----------------
HD constexpr double creduce(double x){
  while (x >  kPI) x -= 2.0 * kPI;
  while (x < -kPI) x += 2.0 * kPI;
  return x;
}
HD constexpr double csin(double x){
  x = creduce(x);
  double t = x, s = x, x2 = x * x;
  for (int i = 1; i < 26; ++i){ t *= -x2 / (double)((2*i) * (2*i + 1)); s += t; }
  return s;
}
HD constexpr double ccos(double x){
  x = creduce(x);
  double t = 1.0, s = 1.0, x2 = x * x;
  for (int i = 1; i < 26; ++i){ t *= -x2 / (double)((2*i - 1) * (2*i)); s += t; }
  return s;
}
HD constexpr double clog(double x){
  double r = x, k = 0.0;
  while (r > 1.25) { r *= 0.5; k += 1.0; }
  while (r < 0.75) { r *= 2.0; k -= 1.0; }
  double z = (r - 1.0) / (r + 1.0), z2 = z * z, term = z, s = z;
  for (int i = 1; i < 60; ++i){ term *= z2; s += term / (double)(2*i + 1); }
  return 2.0 * s + k * 0.69314718055994530942;
}

// ---------------- mel filterbank, 2-sparse per spectral bin ----------------
HD constexpr double hz2mel(double f){ return 1127.0 * clog(1.0 + f / 700.0); }
HD constexpr double mel_lo(){ return hz2mel(80.0); }
HD constexpr double mel_step(){ return (hz2mel(7600.0) - hz2mel(80.0)) / 81.0; }
HD constexpr double bin_mel(int k){ return hz2mel(8000.0 * (double)k / 64.0); }

struct MelEnt { int ja; int jb; float wa; float wb; };

HD constexpr MelEnt mel_ent(int k){
  MelEnt e{-1, -1, 0.0f, 0.0f};
  double u = (bin_mel(k) - mel_lo()) / mel_step();
  if (u <= 0.0 || u >= 81.0) return e;
  int i = (int)u;
  double scale = (k == 32 || k == 64) ? 2.0 : 1.0;
  double wu = ((double)(i + 1) - u) * scale;
  double wl = (u - (double)i) * scale;
  if (i - 1 >= 0 && i - 1 <= 79){ e.ja = i - 1; e.wa = (float)wu; }
  if (i <= 79){ e.jb = i; e.wb = (float)wl; }
  return e;
}
HD constexpr bool bin_used(int k){
  MelEnt e = mel_ent(k);
  return e.ja >= 0 || e.jb >= 0;
}

// Emission order = exact runtime order of the fused final loop:
// idx 0: bin 32; idx 1..60: r=1..15, sub order (r, 64-r, 32-r, 32+r); idx 61,62: bins 16, 48.
HD constexpr int emit_bin(int idx){
  if (idx == 0) return 32;
  if (idx <= 60){
    int r = (idx - 1) / 4 + 1, sub = (idx - 1) % 4;
    return sub == 0 ? r : sub == 1 ? 64 - r : sub == 2 ? 32 - r : 32 + r;
  }
  return idx == 61 ? 16 : 48;
}
HD constexpr int targ(int bin, int slot){
  MelEnt e = mel_ent(bin);
  return slot ? e.jb : e.ja;
}
HD constexpr int emit_pos(int bin){
  for (int idx = 0; idx < 63; ++idx) if (emit_bin(idx) == bin) return idx;
  return -1;
}
HD constexpr bool is_first_touch(int bin, int slot){
  int j = targ(bin, slot);
  if (j < 0) return false;
  int pos = emit_pos(bin);
  for (int idx = 0; idx < pos; ++idx){
    int b2 = emit_bin(idx);
    if (targ(b2, 0) == j || targ(b2, 1) == j) return false;
  }
  if (slot == 1 && targ(bin, 0) == j) return false;
  return true;
}
HD constexpr bool mel_used(int j){
  for (int idx = 0; idx < 63; ++idx){
    int b2 = emit_bin(idx);
    if (targ(b2, 0) == j || targ(b2, 1) == j) return true;
  }
  return false;
}
HD constexpr int bitrev6(int n){
  int r = 0;
  for (int b = 0; b < 6; ++b) r |= ((n >> b) & 1) << (5 - b);
  return r;
}

// pre-halved Hann window: 0.5 * (0.5 - 0.5*cos(2*pi*m/128))
HD constexpr float hwin(int m){
  return (float)(0.5 * (0.5 - 0.5 * ccos(2.0 * kPI * (double)m / 128.0)));
}

// ---------------- magnitude: MUFU.SQRT, floor guard via FMNMX ----------------
DEV float magf(float re, float im){
  float p2 = fmaf(re, re, im * im);
  p2 = fmaxf(p2, 1e-37f);
  float m;
  asm("sqrt.approx.f32 %0, %1;" : "=f"(m) : "f"(p2));
  return m;
}

// ---------------- mel scatter (static register indices, proven) ----------------
template<int BIN>
DEV void scatter(float* mel, float mag){
  constexpr MelEnt e = mel_ent(BIN);
  if constexpr (e.ja >= 0){
    if constexpr (is_first_touch(BIN, 0)) mel[e.ja] = e.wa * mag;
    else mel[e.ja] = fmaf(e.wa, mag, mel[e.ja]);
  }
  if constexpr (e.jb >= 0){
    if constexpr (is_first_touch(BIN, 1)) mel[e.jb] = e.wb * mag;
    else mel[e.jb] = fmaf(e.wb, mag, mel[e.jb]);
  }
}

// ---------------- fused window + bit-reversed load + stage-0 butterfly ----------------
template<int M> struct Fused0 {
  static DEV void run(float* Ar, float* Ai, const float* sx, int tid){
    constexpr int s0 = bitrev6(2*M);
    constexpr int s1 = bitrev6(2*M + 1);          // = s0 + 32
    constexpr float w0r = hwin(2*s0), w0i = hwin(2*s0 + 1);
    constexpr float w1r = hwin(2*s1), w1i = hwin(2*s1 + 1);
    float x0r = sx[tid + 2*s0], x0i = sx[tid + 2*s0 + 1];
    float x1r = sx[tid + 2*s1], x1i = sx[tid + 2*s1 + 1];
    float tr = x1r * w1r;
    float ti = x1i * w1i;
    if constexpr (w0r == 0.0f){                   // only s0 == 0 (window zero at m=0)
      Ar[2*M]     = tr;
      Ar[2*M + 1] = -tr;
    } else {
      Ar[2*M]     = fmaf(x0r, w0r,  tr);
      Ar[2*M + 1] = fmaf(x0r, w0r, -tr);
    }
    Ai[2*M]     = fmaf(x0i, w0i,  ti);
    Ai[2*M + 1] = fmaf(x0i, w0i, -ti);
    Fused0<M + 1>::run(Ar, Ai, sx, tid);
  }
};
template<> struct Fused0<32>{ static DEV void run(float*, float*, const float*, int){} };

// ---------------- radix-2 stage 1 (all twiddles trivial: 1 and -i) ----------------
template<int M> struct Stage1 {
  static DEV void run(float* Ar, float* Ai){
    constexpr int j  = M & 1;
    constexpr int i0 = ((M >> 1) << 2) + j;
    constexpr int i1 = i0 + 2;
    float br_ = Ar[i1], bi_ = Ai[i1];
    float tr, ti;
    if constexpr (j == 0){ tr = br_; ti = bi_; }
    else { tr = bi_; ti = -br_; }                 // w = -i
    float ar_ = Ar[i0], ai_ = Ai[i0];
    Ar[i0] = ar_ + tr; Ai[i0] = ai_ + ti;
    Ar[i1] = ar_ - tr; Ai[i1] = ai_ - ti;
    Stage1<M + 1>::run(Ar, Ai);
  }
};
template<> struct Stage1<32>{ static DEV void run(float*, float*){} };

// ---------------- radix-4 dragonfly: fuses radix-2 stages 2 and 3 ----------------
template<int S, int G> struct R4Loop {
  static DEV void run(float* Ar, float* Ai){
    constexpr int h  = 1 << S;
    constexpr int j  = G & (h - 1);
    constexpr int i0 = ((G >> S) << (S + 2)) + j;
    constexpr double ang = kPI * (double)j / (double)(2 * h);
    constexpr float c1 = (float)ccos(2.0 * ang), s1 = (float)csin(2.0 * ang);
    constexpr float c2 = (float)ccos(ang),        s2 = (float)csin(ang);
    constexpr float c3 = (float)ccos(3.0 * ang),  s3 = (float)csin(3.0 * ang);

    float x0r = Ar[i0],       x0i = Ai[i0];
    float x1r = Ar[i0 + h],   x1i = Ai[i0 + h];
    float x2r = Ar[i0 + 2*h], x2i = Ai[i0 + 2*h];
    float x3r = Ar[i0 + 3*h], x3i = Ai[i0 + 3*h];

    float u1r, u1i, u2r, u2i, u3r, u3i;
    if constexpr (j == 0){
      u1r = x2r; u1i = x2i; u2r = x1r; u2i = x1i; u3r = x3r; u3i = x3i;
    } else {
      u1r = fmaf(c2, x2r,  s2 * x2i);
      u1i = fmaf(c2, x2i, -(s2 * x2r));
      u3r = fmaf(c3, x3r,  s3 * x3i);
      u3i = fmaf(c3, x3i, -(s3 * x3r));
      if constexpr (2*j == h){
        u2r = x1i; u2i = -x1r;
      } else {
        u2r = fmaf(c1, x1r,  s1 * x1i);
        u2i = fmaf(c1, x1i, -(s1 * x1r));
      }
    }
    float r0r = x0r + u2r, r0i = x0i + u2i;
    float r1r = x0r - u2r, r1i = x0i - u2i;
    float pr  = u1r + u3r, pi  = u1i + u3i;
    float qr  = u1r - u3r, qi  = u1i - u3i;

    Ar[i0]       = r0r + pr;  Ai[i0]       = r0i + pi;
    Ar[i0 + 2*h] = r0r - pr;  Ai[i0 + 2*h] = r0i - pi;
    Ar[i0 + h]   = r1r + qi;  Ai[i0 + h]   = r1i - qr;
    Ar[i0 + 3*h] = r1r - qi;  Ai[i0 + 3*h] = r1i + qr;
    R4Loop<S, G + 1>::run(Ar, Ai);
  }
};
template<int S> struct R4Loop<S, 16>{ static DEV void run(float*, float*){} };

// ---------------- radix-2 stage 4 (h = 16) ----------------
template<int M> struct Stage4 {
  static DEV void run(float* Ar, float* Ai){
    constexpr int j  = M & 15;
    constexpr int i0 = ((M >> 4) << 5) + j;
    constexpr int i1 = i0 + 16;
    float br_ = Ar[i1], bi_ = Ai[i1];
    float tr, ti;
    if constexpr (j == 0){ tr = br_; ti = bi_; }
    else if constexpr (j == 8){ tr = bi_; ti = -br_; }
    else {
      constexpr float c = (float)ccos(kPI * (double)j / 16.0);
      constexpr float s = (float)csin(kPI * (double)j / 16.0);
      tr = fmaf(c, br_,  s * bi_);
      ti = fmaf(c, bi_, -(s * br_));
    }
    float ar_ = Ar[i0], ai_ = Ai[i0];
    Ar[i0] = ar_ + tr; Ai[i0] = ai_ + ti;
    Ar[i1] = ar_ - tr; Ai[i1] = ai_ - ti;
    Stage4<M + 1>::run(Ar, Ai);
  }
};
template<> struct Stage4<32>{ static DEV void run(float*, float*){} };

// ---------------- real-split + magnitude + mel scatter on explicit values ----------------
// P = Z[K], R = Z[64-K]
template<int K>
DEV void do_pair_v(float P, float Q, float R, float S, float* mel){
  float zer = P + R, zei = Q - S;
  float zor = Q + S, zoi = R - P;
  constexpr float c = (float)ccos(kPI * (double)K / 64.0);
  constexpr float s = (float)csin(kPI * (double)K / 64.0);
  float A  = fmaf(c, zor,  s * zoi);
  float Bv = fmaf(c, zoi, -(s * zor));
  scatter<K>(mel, magf(zer + A, zei + Bv));
  if constexpr (bin_used(64 - K)){
    scatter<64 - K>(mel, magf(zer - A, Bv - zei));
  }
}

// ---------------- fused stage-5 + real-split: iteration r does butterflies (r, 32-r)
// and pairs (K=r, K=32-r); all 8 input floats die each iteration.
template<int R> struct Final {
  static DEV void run(float* Ar, float* Ai, float* mel){
    constexpr float c = (float)ccos(kPI * (double)R / 32.0);
    constexpr float s = (float)csin(kPI * (double)R / 32.0);
    // butterfly R: a = pos R, b = pos R+32, w = (c, -s)
    float ar = Ar[R], ai = Ai[R], br = Ar[R+32], bi = Ai[R+32];
    float tr = fmaf(c, br,  s * bi);
    float ti = fmaf(c, bi, -(s * br));
    float zRr  = ar + tr, zRi  = ai + ti;          // Z[R]
    float zRpr = ar - tr, zRpi = ai - ti;          // Z[R+32]
    // butterfly 32-R: a' = pos 32-R, b' = pos 64-R, w = (-c, -s)
    float a2r = Ar[32-R], a2i = Ai[32-R], b2r = Ar[64-R], b2i = Ai[64-R];
    float t2r = fmaf(-c, b2r,  s * b2i);
    float t2i = fmaf(-c, b2i, -(s * b2r));
    float zSr  = a2r + t2r, zSi  = a2i + t2i;      // Z[32-R]
    float zSpr = a2r - t2r, zSpi = a2i - t2i;      // Z[64-R]
    do_pair_v<R>     (zRr, zRi, zSpr, zSpi, mel);  // pair R: Z[R], Z[64-R]
    do_pair_v<32 - R>(zSr, zSi, zRpr, zRpi, mel);  // pair 32-R: Z[32-R], Z[32+R]
    Final<R + 1>::run(Ar, Ai, mel);
  }
};
template<> struct Final<16> {
  static DEV void run(float* Ar, float* Ai, float* mel){
    // butterfly 16: w = -i -> t = (bi, -br)
    float ar = Ar[16], ai = Ai[16], br = Ar[48], bi = Ai[48];
    do_pair_v<16>(ar + bi, ai - br, ar - bi, ai + br, mel);
  }
};

// ---------------- store mel row to SMEM (untouched bins -> literal 0) ----------------
template<int J> struct StoreLoop {
  static DEV void run(float* dst, const float* mel){
    if constexpr (mel_used(J)) dst[J] = mel[J];
    else dst[J] = 0.0f;
    StoreLoop<J + 1>::run(dst, mel);
  }
};
template<> struct StoreLoop<80>{ static DEV void run(float*, const float*){} };

// ---------------- kernel ----------------
static constexpr int TPB = 128;       // one thread = one frame
static constexpr int NCOL = 81;       // 1 raw sample + 80 mel

__global__ void __launch_bounds__(TPB, 4)
mel_kernel(const float* __restrict__ x, float* __restrict__ out){
  __shared__ float sx[TPB + 128];                 // 255 staged samples
  __shared__ __align__(16) float sout[TPB * NCOL];

  const int tid = threadIdx.x;
  const int t0  = blockIdx.x * TPB;
  const float* xrow = x + (size_t)blockIdx.y * 16384;

  #pragma unroll
  for (int i = tid; i < TPB + 127; i += TPB){
    int t = t0 + i;
    sx[i] = (t < 16384) ? xrow[t] : 0.0f;
  }
  __syncthreads();

  float Ar[64], Ai[64], mel[80];
  Fused0<0>::run(Ar, Ai, sx, tid);                // window + bitrev load + stage 0
  Stage1<0>::run(Ar, Ai);                         // stage 1 (trivial twiddles)
  R4Loop<2, 0>::run(Ar, Ai);                      // stages 2+3 fused radix-4
  Stage4<0>::run(Ar, Ai);                         // stage 4 radix-2
  // r = 0 of stage 5: Z[32] = pos0 - pos32 (w = 1); bin 0 excluded by mel matrix.
  scatter<32>(mel, magf(Ar[0] - Ar[32], Ai[0] - Ai[32]));
  Final<1>::run(Ar, Ai, mel);                     // fused stage-5 + realsplit + mag + mel

  // stage 81-float output row in SMEM (stride 81 -> bank-conflict-free)
  float* row = sout + tid * NCOL;
  row[0] = sx[tid];
  StoreLoop<0>::run(row + 1, mel);
  __syncthreads();

  // coalesced float4 copy: 128*81 = 10368 floats = 2592 float4 = 20*128 + 32
  float4* g4 = (float4*)(out + ((size_t)blockIdx.y * 16384 + (size_t)t0) * NCOL);
  const float4* s4 = (const float4*)sout;
  #pragma unroll
  for (int r = 0; r < 20; ++r) g4[tid + 128 * r] = s4[tid + 128 * r];
  if (tid < 32) g4[2560 + tid] = s4[2560 + tid];
}

extern "C" void kernel_launch(void* const* d_in, const int* in_sizes, int n_in,
                              void* d_out, int out_size){
  (void)in_sizes; (void)n_in; (void)out_size;
  const float* x = (const float*)d_in[0];
  float* out = (float*)d_out;
  dim3 grid(16384 / TPB, 16);
  mel_kernel<<<grid, TPB>>>(x, out);
}